// round 12
// baseline (speedup 1.0000x reference)
#include <cuda_runtime.h>
#include <math.h>
#include <cstdint>

// =====================================================================
// FrFTPool, centrosymmetric even/odd decomposition, 512-thread CTAs:
//   GEMM1: Te[p,jh] = sum_{k<64} Xe[p,k]·BE[jh,k] (To with Xo,BO)
//   GEMM2: Oe[i,j] = sum_{p<64} ASE[i,p]·Tpe[p,j] (Oo with ASO,Tpo)
// FFMA2 throughout, 3 block barriers, 8 warps/SMSP for latency hiding.
// =====================================================================

#define NBIG 128
#define NSMALL 64
#define NIMG 256
#define XE_ROW 132        // floats, pitch of Xe/Xo rows (128 used)
#define TS_ROW 66         // float2 pitch of Tpe/Tpo rows (64 used)

typedef unsigned long long u64v;

__device__ __forceinline__ u64v pk2(float lo, float hi) {
    u64v r; asm("mov.b64 %0, {%1, %2};" : "=l"(r) : "f"(lo), "f"(hi)); return r;
}
__device__ __forceinline__ void upk2(float& lo, float& hi, u64v v) {
    asm("mov.b64 {%0, %1}, %2;" : "=f"(lo), "=f"(hi) : "l"(v));
}
__device__ __forceinline__ void ffma2(u64v& d, u64v a, u64v b) {
    asm("fma.rn.f32x2 %0, %1, %2, %0;" : "+l"(d) : "l"(a), "l"(b));
}

// ---------------- device scratch --------------------------------------
__device__ __align__(16) float2 d_M1[NBIG * NBIG];
__device__ __align__(16) float2 d_M2[NBIG * NBIG];
__device__ __align__(16) float2 d_M3[NSMALL * NSMALL];
__device__ __align__(16) float2 d_M4[NSMALL * NSMALL];
__device__ __align__(16) float2 d_BE[64 * 32];
__device__ __align__(16) float2 d_BO[64 * 32];
__device__ __align__(16) float2 d_ASE[64 * 32];
__device__ __align__(16) float2 d_ASO[64 * 32];

__device__ __align__(16) float2 d_Ktab[4][4 * NBIG];
__device__ __align__(16) float2 d_Ctab[4][2 * NBIG];
__device__ float2 d_pref[4];
__device__ int    d_flip[4];

// ---------------- 1) chirp tables (DP sincos, sliced over 32 blocks) --
__global__ void build_tables(const float* __restrict__ order1,
                             const float* __restrict__ order2) {
    int m = blockIdx.x;
    int s = blockIdx.y;
    int N = (m < 2) ? NBIG : NSMALL;
    float ap = ((m == 0) || (m == 2)) ? order1[0] : order2[0];
    if (m >= 2) ap = -ap;

    double a = fmod((double)ap, 4.0);
    if (a < 0.0) a += 4.0;
    int flip = 0;
    if (a > 2.0) { flip = 1; a -= 2.0; }

    double alpha = a * M_PI * 0.5;
    double tana2 = tan(alpha * 0.5);
    double sina  = sin(alpha);
    double c     = M_PI / (4.0 * (double)N * sina);
    double kch   = (M_PI / (double)N) * tana2 * 0.25;

    int t = threadIdx.x;
    int nK = 4 * N - 3;
    int nC = 2 * N - 1;
    int i = s * 128 + t;
    if (i < nK) {
        double mm = (double)(i - (2 * N - 2));
        double sn, co; sincos(c * mm * mm, &sn, &co);
        d_Ktab[m][i] = make_float2((float)co, (float)sn);
    }
    if (t < 32) {
        int p = s * 32 + t;
        if (p < nC) {
            double n = (double)(p - (N - 1));
            double sn, co; sincos(-kch * n * n, &sn, &co);
            d_Ctab[m][p] = make_float2((float)co, (float)sn);
        }
    }
    if (s == 0 && t == 0) {
        double ph = -(1.0 - a) * M_PI * 0.25;
        double sn, co; sincos(ph, &sn, &co);
        double sc = sqrt(c / M_PI);
        d_pref[m] = make_float2((float)(co * sc), (float)(sn * sc));
        d_flip[m] = flip;
    }
}

// ---------------- 2) FrFT matrices from tables (fp32 only) ------------
__global__ void build_matrix() {
    int m = blockIdx.y;
    int N = (m < 2) ? NBIG : NSMALL;
    int j = blockIdx.x;
    if (j >= N) return;

    __shared__ float2 Ks[4 * NBIG];
    __shared__ float2 Cs[2 * NBIG];
    __shared__ float  W[NBIG];
    __shared__ float2 KC[NBIG];

    int tid = threadIdx.x;
    for (int i = tid; i < 4 * N - 3; i += 128) Ks[i] = d_Ktab[m][i];
    for (int p = tid; p < 2 * N - 1; p += 128) Cs[p] = d_Ctab[m][p];
    if (tid < N)
        W[tid] = ((tid & 1) ? -2.0f : 2.0f) / ((float)M_PI * (float)(2 * tid + 1));
    __syncthreads();

    int off = 2 * N - 2;
    if (tid < N - 1) {
        float2 K = Ks[2 * j - 2 * tid - 1 + off];
        float2 C = Cs[2 * tid + 1];
        KC[tid] = make_float2(K.x * C.x - K.y * C.y, K.x * C.y + K.y * C.x);
    }
    __syncthreads();

    int k = tid;
    if (k >= N) return;
    int flip = d_flip[m];
    int kk = flip ? (N - 1 - k) : k;

    float2 Ke = Ks[2 * (j - kk) + off];
    float2 Ce = Cs[2 * kk];
    float sr = Ke.x * Ce.x - Ke.y * Ce.y;
    float si = Ke.x * Ce.y + Ke.y * Ce.x;

    #pragma unroll 4
    for (int t = 0; t < N - 1; t++) {
        int u = t - kk;
        int idx = u ^ (u >> 31);
        float sv = W[idx];
        float2 kc = KC[t];
        sr = fmaf(kc.x, sv, sr);
        si = fmaf(kc.y, sv, si);
    }

    float2 pr = d_pref[m];
    float2 Cj = Cs[2 * j];
    float pcr = pr.x * Cj.x - pr.y * Cj.y;
    float pci = pr.x * Cj.y + pr.y * Cj.x;
    float2 outv;
    outv.x = pcr * sr - pci * si;
    outv.y = pcr * si + pci * sr;

    float2* M = (m == 0) ? d_M1 : (m == 1) ? d_M2 : (m == 2) ? d_M3 : d_M4;
    M[j * N + k] = outv;
}

// ---------------- 3) combine + fold -----------------------------------
__global__ void combine() {
    int jb = blockIdx.x;         // 0..31
    int h = threadIdx.x;         // 0..127
    __shared__ float2 sbuf[128];

    if (blockIdx.y) {            // ---- B side ----
        int k = h & 63;
        int row = (h >> 6) ? (63 - jb) : jb;
        float ar = 0.f, ai = 0.f;
        #pragma unroll 4
        for (int q = 0; q < NSMALL; q++) {
            float2 l2 = d_M3[row * NSMALL + q];
            float2 r2 = d_M1[(32 + q) * NBIG + k];
            ar += l2.x * r2.x - l2.y * r2.y;
            ai += l2.x * r2.y + l2.y * r2.x;
        }
        sbuf[h] = make_float2(ar, ai);
        __syncthreads();
        if (h < 64) {
            float2 a = sbuf[h], b = sbuf[h + 64];
            d_BE[h * 32 + jb] = make_float2(0.5f * (a.x + b.x), 0.5f * (a.y + b.y));
        } else {
            int k2 = h - 64;
            float2 a = sbuf[k2], b = sbuf[h];
            d_BO[k2 * 32 + jb] = make_float2(0.5f * (a.x - b.x), 0.5f * (a.y - b.y));
        }
    } else {                     // ---- A side ----
        float ar = 0.f, ai = 0.f;
        #pragma unroll 4
        for (int p = 0; p < NSMALL; p++) {
            float2 l2 = d_M4[jb * NSMALL + p];
            float2 r2 = d_M2[(32 + p) * NBIG + h];
            ar += l2.x * r2.x - l2.y * r2.y;
            ai += l2.x * r2.y + l2.y * r2.x;
        }
        sbuf[h] = make_float2(ar, ai);
        __syncthreads();
        if (h < 64) {
            float2 a = sbuf[h], b = sbuf[127 - h];
            d_ASE[h * 32 + jb] = make_float2(0.5f * (a.x + b.x), 0.5f * (a.y + b.y));
        } else {
            int p = h - 64;
            float2 a = sbuf[p], b = sbuf[127 - p];
            d_ASO[p * 32 + jb] = make_float2(0.5f * (a.x - b.x), 0.5f * (a.y - b.y));
        }
    }
}

// ---------------- 4) main fused kernel (512 threads) -------------------
#define SMEM_BYTES (2 * 64 * XE_ROW * 4 + 2 * 64 * 32 * 8)   // 67584 + 32768

__global__ __launch_bounds__(512, 2)
void frft_pool_main(const float* __restrict__ x, float* __restrict__ out) {
    extern __shared__ float smem[];
    float*  Xe   = smem;                               // [64][132]
    float*  Xo   = smem + 64 * XE_ROW;                 // [64][132]
    float2* Tile = (float2*)(smem + 2 * 64 * XE_ROW);  // 4096 float2

    int tid = threadIdx.x;
    int l = tid & 31;
    int w = tid >> 5;          // 0..15
    int img = blockIdx.x;

    // ---- load X, fold even/odd: Xe[k][p] = X[p,k]+X[p,127-k] ----
    const float4* xg4 = (const float4*)(x + (size_t)img * (NBIG * NBIG));
    #pragma unroll
    for (int it = 0; it < 4; it++) {
        int idx = tid + it * 512;        // 2048 tasks: p<128 x quad<16
        int p = idx >> 4;
        int q = idx & 15;
        float4 v1 = xg4[p * 32 + q];
        float4 v2 = xg4[p * 32 + 31 - q];
        Xe[(4 * q + 0) * XE_ROW + p] = v1.x + v2.w;
        Xe[(4 * q + 1) * XE_ROW + p] = v1.y + v2.z;
        Xe[(4 * q + 2) * XE_ROW + p] = v1.z + v2.y;
        Xe[(4 * q + 3) * XE_ROW + p] = v1.w + v2.x;
        Xo[(4 * q + 0) * XE_ROW + p] = v1.x - v2.w;
        Xo[(4 * q + 1) * XE_ROW + p] = v1.y - v2.z;
        Xo[(4 * q + 2) * XE_ROW + p] = v1.z - v2.y;
        Xo[(4 * q + 3) * XE_ROW + p] = v1.w - v2.x;
    }
    // ---- stage BE+BO tiles (32KB) ----
    {
        const ulonglong2* g = (const ulonglong2*)d_BE;
        ulonglong2* t = (ulonglong2*)Tile;
        t[tid]       = g[tid];
        t[tid + 512] = g[tid + 512];
        g = (const ulonglong2*)d_BO;
        t[1024 + tid]       = g[tid];
        t[1024 + tid + 512] = g[tid + 512];
    }
    __syncthreads();                                   // B1

    // ---- GEMM1: rows {p, 127-p}, p = l + 32*(w>>3); jh cols 4(w&7).. ----
    int wp = w >> 3;
    int w8 = w & 7;
    int p = l + 32 * wp;
    int mp = 127 - p;
    int jb = 4 * w8;

    u64v aTe[2][4], aTo[2][4];
    #pragma unroll
    for (int r = 0; r < 2; r++)
        #pragma unroll
        for (int jj = 0; jj < 4; jj++) { aTe[r][jj] = 0ull; aTo[r][jj] = 0ull; }

    const float2* BEt = Tile;            // [64][32]
    const float2* BOt = Tile + 64 * 32;

    #pragma unroll 8
    for (int k = 0; k < 64; k++) {
        float xeP = Xe[k * XE_ROW + p];
        float xeM = Xe[k * XE_ROW + mp];
        float xoP = Xo[k * XE_ROW + p];
        float xoM = Xo[k * XE_ROW + mp];
        const ulonglong2* bep = (const ulonglong2*)&BEt[k * 32 + jb];
        ulonglong2 beA = bep[0], beB = bep[1];
        const ulonglong2* bop = (const ulonglong2*)&BOt[k * 32 + jb];
        ulonglong2 boA = bop[0], boB = bop[1];
        u64v be4[4] = {beA.x, beA.y, beB.x, beB.y};
        u64v bo4[4] = {boA.x, boA.y, boB.x, boB.y};
        u64v xE0 = pk2(xeP, xeP), xE1 = pk2(xeM, xeM);
        u64v xO0 = pk2(xoP, xoP), xO1 = pk2(xoM, xoM);
        #pragma unroll
        for (int jj = 0; jj < 4; jj++) {
            ffma2(aTe[0][jj], xE0, be4[jj]);
            ffma2(aTe[1][jj], xE1, be4[jj]);
            ffma2(aTo[0][jj], xO0, bo4[jj]);
            ffma2(aTo[1][jj], xO1, bo4[jj]);
        }
    }

    __syncthreads();                                   // B2: GEMM1 reads done

    // ---- stage ASE+ASO tiles (overwrites BE/BO) ----
    {
        const ulonglong2* g = (const ulonglong2*)d_ASE;
        ulonglong2* t = (ulonglong2*)Tile;
        t[tid]       = g[tid];
        t[tid + 512] = g[tid + 512];
        g = (const ulonglong2*)d_ASO;
        t[1024 + tid]       = g[tid];
        t[1024 + tid + 512] = g[tid + 512];
    }

    // ---- fold T (thread-local): rows p & 127-p -> Tpe/Tpo row p ----
    float2* Tpe = (float2*)smem;                 // [64][66]
    float2* Tpo = (float2*)(smem + 64 * XE_ROW); // [64][66]
    #pragma unroll
    for (int jj = 0; jj < 4; jj++) {
        int jh = jb + jj;
        float ePr, ePi, oPr, oPi, eMr, eMi, oMr, oMi;
        upk2(ePr, ePi, aTe[0][jj]);
        upk2(oPr, oPi, aTo[0][jj]);
        upk2(eMr, eMi, aTe[1][jj]);
        upk2(oMr, oMi, aTo[1][jj]);
        // T[p][jh] = Te[p]+To[p]; T[p][63-jh] = Te[p]-To[p]; same for 127-p
        float TPjr = ePr + oPr, TPji = ePi + oPi;
        float TPmr = ePr - oPr, TPmi = ePi - oPi;
        float TMjr = eMr + oMr, TMji = eMi + oMi;
        float TMmr = eMr - oMr, TMmi = eMi - oMi;
        Tpe[p * TS_ROW + jh]        = make_float2(TPjr + TMjr, TPji + TMji);
        Tpo[p * TS_ROW + jh]        = make_float2(TPjr - TMjr, TPji - TMji);
        Tpe[p * TS_ROW + (63 - jh)] = make_float2(TPmr + TMmr, TPmi + TMmi);
        Tpo[p * TS_ROW + (63 - jh)] = make_float2(TPmr - TMmr, TPmi - TMmi);
    }
    __syncthreads();                                   // B3

    // ---- GEMM2: i = l (<32), j cols 4w..4w+3 ----
    int jb2 = 4 * w;
    u64v accAe[4], accBe[4], accAo[4], accBo[4];
    #pragma unroll
    for (int jj = 0; jj < 4; jj++) {
        accAe[jj] = 0ull; accBe[jj] = 0ull; accAo[jj] = 0ull; accBo[jj] = 0ull;
    }

    const float2* ASEt = Tile;            // [64][32]
    const float2* ASOt = Tile + 64 * 32;

    #pragma unroll 8
    for (int pz = 0; pz < 64; pz++) {
        float2 ase = ASEt[pz * 32 + l];
        float2 aso = ASOt[pz * 32 + l];
        const ulonglong2* tep = (const ulonglong2*)&Tpe[pz * TS_ROW + jb2];
        ulonglong2 teA = tep[0], teB = tep[1];
        const ulonglong2* top = (const ulonglong2*)&Tpo[pz * TS_ROW + jb2];
        ulonglong2 toA = top[0], toB = top[1];
        u64v te[4] = {teA.x, teA.y, teB.x, teB.y};
        u64v to[4] = {toA.x, toA.y, toB.x, toB.y};
        u64v axe = pk2(ase.x, ase.x), aye = pk2(ase.y, ase.y);
        u64v axo = pk2(aso.x, aso.x), ayo = pk2(aso.y, aso.y);
        #pragma unroll
        for (int jj = 0; jj < 4; jj++) {
            ffma2(accAe[jj], axe, te[jj]);
            ffma2(accBe[jj], aye, te[jj]);
            ffma2(accAo[jj], axo, to[jj]);
            ffma2(accBo[jj], ayo, to[jj]);
        }
    }

    // ---- epilogue: O[l][j] = Oe+Oo, O[63-l][j] = Oe-Oo ----
    float* og = out + (size_t)img * (NSMALL * NSMALL);
    float r0[4], r1[4];
    #pragma unroll
    for (int jj = 0; jj < 4; jj++) {
        float Aer, Aei, Ber, Bei, Aor, Aoi, Bor, Boi;
        upk2(Aer, Aei, accAe[jj]);
        upk2(Ber, Bei, accBe[jj]);
        upk2(Aor, Aoi, accAo[jj]);
        upk2(Bor, Boi, accBo[jj]);
        float Oer = Aer - Bei, Oei = Aei + Ber;
        float Oor = Aor - Boi, Ooi = Aoi + Bor;
        float ar = Oer + Oor, ai = Oei + Ooi;
        float br = Oer - Oor, bi = Oei - Ooi;
        r0[jj] = sqrtf(ar * ar + ai * ai);
        r1[jj] = sqrtf(br * br + bi * bi);
    }
    *(float4*)&og[l * NSMALL + jb2]        = make_float4(r0[0], r0[1], r0[2], r0[3]);
    *(float4*)&og[(63 - l) * NSMALL + jb2] = make_float4(r1[0], r1[1], r1[2], r1[3]);
}

// ---------------------------------------------------------------------
extern "C" void kernel_launch(void* const* d_in, const int* in_sizes, int n_in,
                              void* d_out, int out_size) {
    const float* x  = (const float*)d_in[0];
    const float* o1 = (const float*)d_in[1];
    const float* o2 = (const float*)d_in[2];
    float* out = (float*)d_out;

    build_tables<<<dim3(4, 8), 128>>>(o1, o2);
    build_matrix<<<dim3(NBIG, 4), 128>>>();
    combine<<<dim3(32, 2), 128>>>();

    cudaFuncSetAttribute(frft_pool_main,
                         cudaFuncAttributeMaxDynamicSharedMemorySize, SMEM_BYTES);
    frft_pool_main<<<NIMG, 512, SMEM_BYTES>>>(x, out);
}

// round 13
// speedup vs baseline: 1.2204x; 1.2204x over previous
#include <cuda_runtime.h>
#include <cuda_bf16.h>
#include <math.h>
#include <cstdint>

// =====================================================================
// FrFTPool via mma.sync (sm_80 HMMA path, valid on compute_103):
//  GEMM1: D[n,p] = sum_k Baug[n,k]·Xaug[p,k]   n<128 (j,ri), p<128
//  GEMM2: D2[r,j] = sum_k A2aug[r,k]·Taug[j,k] r<128 (i,ri), j<64
//  out[i,j] = sqrt(D2[i,j]^2 + D2[i+64,j]^2)
// bf16 hi/lo split folded into K (3 segments): rel err ~3e-5.
// Constant operands pre-packed in A-fragment layout at prep time.
// =====================================================================

#define NBIG 128
#define NIMG 256
#define P16 136            // smem row pitch in bf16 units (272B: conflict-free)

__device__ __forceinline__ unsigned short bfh(float v) {
    return __bfloat16_as_ushort(__float2bfloat16_rn(v));
}
__device__ __forceinline__ float bff(unsigned short u) {
    return __bfloat162float(__ushort_as_bfloat16(u));
}
__device__ __forceinline__ void ldm_x2(uint32_t& r0, uint32_t& r1, uint32_t sa) {
    asm volatile("ldmatrix.sync.aligned.m8n8.x2.shared.b16 {%0,%1}, [%2];"
                 : "=r"(r0), "=r"(r1) : "r"(sa));
}
__device__ __forceinline__ void mma16816(float* c, uint4 a, uint32_t b0, uint32_t b1) {
    asm volatile("mma.sync.aligned.m16n8k16.row.col.f32.bf16.bf16.f32 "
                 "{%0,%1,%2,%3}, {%4,%5,%6,%7}, {%8,%9}, {%0,%1,%2,%3};"
                 : "+f"(c[0]), "+f"(c[1]), "+f"(c[2]), "+f"(c[3])
                 : "r"(a.x), "r"(a.y), "r"(a.z), "r"(a.w), "r"(b0), "r"(b1));
}

// ---------------- device scratch --------------------------------------
__device__ __align__(16) float2 d_M1[NBIG * NBIG];
__device__ __align__(16) float2 d_M2[NBIG * NBIG];
__device__ __align__(16) float2 d_M3[64 * 64];
__device__ __align__(16) float2 d_M4[64 * 64];
__device__ __align__(16) float2 d_Ac[64 * 128];       // A = M4·M2[32:96]
__device__ __align__(16) float2 d_Bc[64 * 128];       // B = M3·M1[32:96]
__device__ __align__(16) uint4  d_AF1[192 * 32];      // GEMM1 A-frags (8 mt x 24 kt)
__device__ __align__(16) uint4  d_AF2[384 * 32];      // GEMM2 A-frags (8 mt x 48 kt)

__device__ __align__(16) float2 d_Ktab[4][4 * NBIG];
__device__ __align__(16) float2 d_Ctab[4][2 * NBIG];
__device__ float2 d_pref[4];
__device__ int    d_flip[4];

// ---------------- 1) chirp tables (DP sincos, sliced over 32 blocks) --
__global__ void build_tables(const float* __restrict__ order1,
                             const float* __restrict__ order2) {
    int m = blockIdx.x;
    int s = blockIdx.y;
    int N = (m < 2) ? NBIG : 64;
    float ap = ((m == 0) || (m == 2)) ? order1[0] : order2[0];
    if (m >= 2) ap = -ap;

    double a = fmod((double)ap, 4.0);
    if (a < 0.0) a += 4.0;
    int flip = 0;
    if (a > 2.0) { flip = 1; a -= 2.0; }

    double alpha = a * M_PI * 0.5;
    double tana2 = tan(alpha * 0.5);
    double sina  = sin(alpha);
    double c     = M_PI / (4.0 * (double)N * sina);
    double kch   = (M_PI / (double)N) * tana2 * 0.25;

    int t = threadIdx.x;
    int i = s * 128 + t;
    if (i < 4 * N - 3) {
        double mm = (double)(i - (2 * N - 2));
        double sn, co; sincos(c * mm * mm, &sn, &co);
        d_Ktab[m][i] = make_float2((float)co, (float)sn);
    }
    if (t < 32) {
        int p = s * 32 + t;
        if (p < 2 * N - 1) {
            double n = (double)(p - (N - 1));
            double sn, co; sincos(-kch * n * n, &sn, &co);
            d_Ctab[m][p] = make_float2((float)co, (float)sn);
        }
    }
    if (s == 0 && t == 0) {
        double ph = -(1.0 - a) * M_PI * 0.25;
        double sn, co; sincos(ph, &sn, &co);
        double sc = sqrt(c / M_PI);
        d_pref[m] = make_float2((float)(co * sc), (float)(sn * sc));
        d_flip[m] = flip;
    }
}

// ---------------- 2) FrFT matrices from tables (fp32 only) ------------
__global__ void build_matrix() {
    int m = blockIdx.y;
    int N = (m < 2) ? NBIG : 64;
    int j = blockIdx.x;
    if (j >= N) return;

    __shared__ float2 Ks[4 * NBIG];
    __shared__ float2 Cs[2 * NBIG];
    __shared__ float  W[NBIG];
    __shared__ float2 KC[NBIG];

    int tid = threadIdx.x;
    for (int i = tid; i < 4 * N - 3; i += 128) Ks[i] = d_Ktab[m][i];
    for (int p = tid; p < 2 * N - 1; p += 128) Cs[p] = d_Ctab[m][p];
    if (tid < N)
        W[tid] = ((tid & 1) ? -2.0f : 2.0f) / ((float)M_PI * (float)(2 * tid + 1));
    __syncthreads();

    int off = 2 * N - 2;
    if (tid < N - 1) {
        float2 K = Ks[2 * j - 2 * tid - 1 + off];
        float2 C = Cs[2 * tid + 1];
        KC[tid] = make_float2(K.x * C.x - K.y * C.y, K.x * C.y + K.y * C.x);
    }
    __syncthreads();

    int k = tid;
    if (k >= N) return;
    int flip = d_flip[m];
    int kk = flip ? (N - 1 - k) : k;

    float2 Ke = Ks[2 * (j - kk) + off];
    float2 Ce = Cs[2 * kk];
    float sr = Ke.x * Ce.x - Ke.y * Ce.y;
    float si = Ke.x * Ce.y + Ke.y * Ce.x;

    #pragma unroll 4
    for (int t = 0; t < N - 1; t++) {
        int u = t - kk;
        int idx = u ^ (u >> 31);
        float sv = W[idx];
        float2 kc = KC[t];
        sr = fmaf(kc.x, sv, sr);
        si = fmaf(kc.y, sv, si);
    }

    float2 pr = d_pref[m];
    float2 Cj = Cs[2 * j];
    float pcr = pr.x * Cj.x - pr.y * Cj.y;
    float pci = pr.x * Cj.y + pr.y * Cj.x;
    float2 outv;
    outv.x = pcr * sr - pci * si;
    outv.y = pcr * si + pci * sr;

    float2* M = (m == 0) ? d_M1 : (m == 1) ? d_M2 : (m == 2) ? d_M3 : d_M4;
    M[j * N + k] = outv;
}

// ---------------- 3) combine: A = M4·M2[32:96], B = M3·M1[32:96] ------
__global__ void combine() {
    int i = blockIdx.x;          // 0..63
    int h = threadIdx.x;         // 0..127
    const float2* L = blockIdx.y ? d_M3 : d_M4;   // 64x64
    const float2* R = blockIdx.y ? d_M1 : d_M2;   // 128x128
    float ar = 0.f, ai = 0.f;
    #pragma unroll 4
    for (int p = 0; p < 64; p++) {
        float2 l2 = L[i * 64 + p];
        float2 r2 = R[(32 + p) * NBIG + h];
        ar += l2.x * r2.x - l2.y * r2.y;
        ai += l2.x * r2.y + l2.y * r2.x;
    }
    float2* T = blockIdx.y ? d_Bc : d_Ac;
    T[i * 128 + h] = make_float2(ar, ai);
}

// ---------------- 4) fragpack: constant operands in A-frag layout ------
// GEMM1 A-side = Baug [128n x 384k], segs k: [Bh | Bh | Bl]
//   n<64: Re(B[n][kk]); n>=64: Im(B[n-64][kk])
// GEMM2 A-side = A2aug [128r x 768k], segs: [A2h | A2l | A2h]
//   k256 = k%256; ri=k256/128; p=k256%128
//   r<64:  ri? -Ai[r][p]  : Ar[r][p]
//   r>=64: ri?  Ar[r-64][p] : Ai[r-64][p]
__device__ __forceinline__ uint32_t packB1(int n, int kk, int seg) {
    uint32_t r = 0;
    #pragma unroll
    for (int e = 0; e < 2; e++) {
        float2 b = d_Bc[(n & 63) * 128 + kk + e];
        float v = (n < 64) ? b.x : b.y;
        unsigned short hh = bfh(v);
        unsigned short u = (seg == 2) ? bfh(v - bff(hh)) : hh;
        r |= ((uint32_t)u) << (16 * e);
    }
    return r;
}
__device__ __forceinline__ uint32_t packA2(int rr, int c, int seg) {
    uint32_t r = 0;
    #pragma unroll
    for (int e = 0; e < 2; e++) {
        int cc = c + e;
        int ri = cc >> 7, p = cc & 127;
        float2 a = d_Ac[(rr & 63) * 128 + p];
        float v = (rr < 64) ? (ri ? -a.y : a.x) : (ri ? a.x : a.y);
        unsigned short hh = bfh(v);
        unsigned short u = (seg == 1) ? bfh(v - bff(hh)) : hh;
        r |= ((uint32_t)u) << (16 * e);
    }
    return r;
}
__global__ void fragpack() {
    int idx = blockIdx.x * 256 + threadIdx.x;     // < 18432
    int lane = idx & 31, t = idx >> 5;
    if (t < 192) {
        int mt = t / 24, kt = t % 24;
        int seg = kt >> 3, kb = (kt & 7) * 16;
        int r0 = 16 * mt + (lane >> 2);
        int c0 = kb + 2 * (lane & 3);
        uint4 o;
        o.x = packB1(r0,     c0,     seg);
        o.y = packB1(r0 + 8, c0,     seg);
        o.z = packB1(r0,     c0 + 8, seg);
        o.w = packB1(r0 + 8, c0 + 8, seg);
        d_AF1[t * 32 + lane] = o;
    } else {
        int t2 = t - 192;
        int mt = t2 / 48, kt = t2 % 48;
        int seg = kt >> 4;
        int k256 = (kt & 15) * 16;
        int r0 = 16 * mt + (lane >> 2);
        int c0 = k256 + 2 * (lane & 3);
        uint4 o;
        o.x = packA2(r0,     c0,     seg);
        o.y = packA2(r0 + 8, c0,     seg);
        o.z = packA2(r0,     c0 + 8, seg);
        o.w = packA2(r0 + 8, c0 + 8, seg);
        d_AF2[t2 * 32 + lane] = o;
    }
}

// ---------------- 5) main tensor kernel --------------------------------
#define SMEM_BYTES (2 * 128 * P16 * 2)   // 69632: two bf16 planes [128][136]

__global__ __launch_bounds__(256, 2)
void frft_pool_main(const float* __restrict__ x, float* __restrict__ out) {
    extern __shared__ char smem[];
    unsigned short* Xh = (unsigned short*)smem;   // plane0 [128][136]
    unsigned short* Xl = Xh + 128 * P16;          // plane1
    uint32_t sbase;
    {
        uint64_t g = (uint64_t)__cvta_generic_to_shared(smem);
        sbase = (uint32_t)g;
    }
    uint32_t plane0 = sbase;
    uint32_t plane1 = sbase + 128 * P16 * 2;

    int tid = threadIdx.x;
    int lane = tid & 31;
    int w = tid >> 5;          // warp 0..7
    int img = blockIdx.x;
    int gr = lane >> 2;        // group row 0..7
    int gc = 2 * (lane & 3);   // 0,2,4,6

    // ---- A) load X, split to bf16 h/l planes (row-major [p][k]) ----
    const float4* xg4 = (const float4*)(x + (size_t)img * (NBIG * NBIG));
    #pragma unroll
    for (int it = 0; it < 16; it++) {
        int idx = tid + it * 256;
        int p = idx >> 5;
        int q4 = (idx & 31) << 2;
        float4 v = xg4[idx];
        unsigned short h0 = bfh(v.x), h1 = bfh(v.y), h2 = bfh(v.z), h3 = bfh(v.w);
        uint2 hv, lv;
        hv.x = (uint32_t)h0 | ((uint32_t)h1 << 16);
        hv.y = (uint32_t)h2 | ((uint32_t)h3 << 16);
        lv.x = (uint32_t)bfh(v.x - bff(h0)) | ((uint32_t)bfh(v.y - bff(h1)) << 16);
        lv.y = (uint32_t)bfh(v.z - bff(h2)) | ((uint32_t)bfh(v.w - bff(h3)) << 16);
        *(uint2*)&Xh[p * P16 + q4] = hv;
        *(uint2*)&Xl[p * P16 + q4] = lv;
    }
    __syncthreads();                               // B1

    // ---- B) GEMM1: D[n,p] = Baug·Xaug^T;  warp w owns n rows 16w..16w+15
    float c[16][4];
    #pragma unroll
    for (int nt = 0; nt < 16; nt++)
        #pragma unroll
        for (int r = 0; r < 4; r++) c[nt][r] = 0.f;

    #pragma unroll 4
    for (int kt = 0; kt < 24; kt++) {
        uint4 af = d_AF1[(w * 24 + kt) * 32 + lane];
        uint32_t plane = ((kt >> 3) == 1) ? plane1 : plane0;  // X segs [h|l|h]
        int kb = (kt & 7) * 16;
        uint32_t ab = plane + (uint32_t)(((lane & 7) * P16 + kb + 8 * ((lane >> 3) & 1)) * 2);
        #pragma unroll
        for (int nt = 0; nt < 16; nt++) {
            uint32_t b0, b1;
            ldm_x2(b0, b1, ab + (uint32_t)(nt * 8 * P16 * 2));
            mma16816(c[nt], af, b0, b1);
        }
    }
    __syncthreads();                               // B2: X reads done

    // ---- C) split-store T planes (reuse smem): T[n][p] bf16 h/l ----
    unsigned short* Th = Xh;
    unsigned short* Tl = Xl;
    #pragma unroll
    for (int nt = 0; nt < 16; nt++) {
        int p = nt * 8 + gc;
        int n0 = 16 * w + gr;
        unsigned short hA0 = bfh(c[nt][0]), hA1 = bfh(c[nt][1]);
        unsigned short hB0 = bfh(c[nt][2]), hB1 = bfh(c[nt][3]);
        *(uint32_t*)&Th[n0 * P16 + p] =
            (uint32_t)hA0 | ((uint32_t)hA1 << 16);
        *(uint32_t*)&Tl[n0 * P16 + p] =
            (uint32_t)bfh(c[nt][0] - bff(hA0)) |
            ((uint32_t)bfh(c[nt][1] - bff(hA1)) << 16);
        *(uint32_t*)&Th[(n0 + 8) * P16 + p] =
            (uint32_t)hB0 | ((uint32_t)hB1 << 16);
        *(uint32_t*)&Tl[(n0 + 8) * P16 + p] =
            (uint32_t)bfh(c[nt][2] - bff(hB0)) |
            ((uint32_t)bfh(c[nt][3] - bff(hB1)) << 16);
    }
    __syncthreads();                               // B3

    // ---- D) GEMM2: D2[r,j] = A2aug·Taug^T; warp w owns r rows 16w.. ----
    float d2[8][4];
    #pragma unroll
    for (int jt = 0; jt < 8; jt++)
        #pragma unroll
        for (int r = 0; r < 4; r++) d2[jt][r] = 0.f;

    #pragma unroll 4
    for (int kt = 0; kt < 48; kt++) {
        uint4 af = d_AF2[(w * 48 + kt) * 32 + lane];
        int seg = kt >> 4;
        uint32_t plane = (seg == 2) ? plane1 : plane0;   // T segs [h|h|l]
        int k256 = (kt & 15) * 16;
        int ri = k256 >> 7, kp = k256 & 127;
        uint32_t ab = plane + (uint32_t)((((64 * ri) + (lane & 7)) * P16 +
                                          kp + 8 * ((lane >> 3) & 1)) * 2);
        #pragma unroll
        for (int jt = 0; jt < 8; jt++) {
            uint32_t b0, b1;
            ldm_x2(b0, b1, ab + (uint32_t)(jt * 8 * P16 * 2));
            mma16816(d2[jt], af, b0, b1);
        }
    }
    __syncthreads();                               // B4: T reads done

    // ---- E) D2 -> smem f32 [128][68] ----
    float* D2s = (float*)smem;
    #pragma unroll
    for (int jt = 0; jt < 8; jt++) {
        int j = jt * 8 + gc;
        int r0 = 16 * w + gr;
        *(float2*)&D2s[r0 * 68 + j]       = make_float2(d2[jt][0], d2[jt][1]);
        *(float2*)&D2s[(r0 + 8) * 68 + j] = make_float2(d2[jt][2], d2[jt][3]);
    }
    __syncthreads();                               // B5

    // ---- F) magnitudes ----
    float* og = out + (size_t)img * 4096;
    #pragma unroll
    for (int it = 0; it < 4; it++) {
        int idx = tid + it * 256;
        int i = idx >> 4;
        int jq = (idx & 15) << 2;
        float4 vr = *(float4*)&D2s[i * 68 + jq];
        float4 vi = *(float4*)&D2s[(i + 64) * 68 + jq];
        float4 o;
        o.x = sqrtf(vr.x * vr.x + vi.x * vi.x);
        o.y = sqrtf(vr.y * vr.y + vi.y * vi.y);
        o.z = sqrtf(vr.z * vr.z + vi.z * vi.z);
        o.w = sqrtf(vr.w * vr.w + vi.w * vi.w);
        *(float4*)&og[i * 64 + jq] = o;
    }
}

// ---------------------------------------------------------------------
extern "C" void kernel_launch(void* const* d_in, const int* in_sizes, int n_in,
                              void* d_out, int out_size) {
    const float* x  = (const float*)d_in[0];
    const float* o1 = (const float*)d_in[1];
    const float* o2 = (const float*)d_in[2];
    float* out = (float*)d_out;

    build_tables<<<dim3(4, 8), 128>>>(o1, o2);
    build_matrix<<<dim3(NBIG, 4), 128>>>();
    combine<<<dim3(64, 2), 128>>>();
    fragpack<<<72, 256>>>();

    cudaFuncSetAttribute(frft_pool_main,
                         cudaFuncAttributeMaxDynamicSharedMemorySize, SMEM_BYTES);
    frft_pool_main<<<NIMG, 256, SMEM_BYTES>>>(x, out);
}